// round 1
// baseline (speedup 1.0000x reference)
#include <cuda_runtime.h>
#include <math.h>

#define BATCH 4
#define SEQ   4096
#define EMB   2048
#define HD    128
#define MTOT  (BATCH*SEQ)

// Scratch (device globals: no allocation allowed in kernel_launch)
static __device__ float g_Q[MTOT*HD];
static __device__ float g_K[MTOT*HD];
static __device__ float g_V[MTOT*HD];
static __device__ float g_cos[SEQ*(HD/2)];
static __device__ float g_sin[SEQ*(HD/2)];

// ---------------------------------------------------------------------------
// RoPE tables: freq in double (rounded to fp32), angle = fp32(s * freq),
// then fp32 sincos — mirrors the reference's fp32 pipeline.
// ---------------------------------------------------------------------------
__global__ void rope_table_kernel() {
    int idx = blockIdx.x * blockDim.x + threadIdx.x;
    if (idx >= SEQ * (HD/2)) return;
    int s = idx >> 6;          // position
    int i = idx & 63;          // pair index
    // freq = 10000^(-(2i)/128); ln(10000) = 9.210340371976184
    double freqd = exp(-(double)(2*i) * (9.210340371976184 / 128.0));
    float freq = (float)freqd;
    float angle = (float)s * freq;
    float sn, cs;
    sincosf(angle, &sn, &cs);
    g_cos[idx] = cs;
    g_sin[idx] = sn;
}

// ---------------------------------------------------------------------------
// QKV projection: C[M=16384, 128] = x[M, 2048] @ W[2048, 128] + b, RoPE fused
// blockIdx.y selects Q/K/V. 128x128x16 tile, 256 threads, 8x8 microtile.
// ---------------------------------------------------------------------------
#define GBM 128
#define GBK 16

__global__ __launch_bounds__(256, 2) void qkv_gemm_kernel(
    const float* __restrict__ x,
    const float* __restrict__ Wq, const float* __restrict__ Bq,
    const float* __restrict__ Wk, const float* __restrict__ Bk,
    const float* __restrict__ Wv, const float* __restrict__ Bv)
{
    __shared__ float As[GBK][GBM];   // A transposed: As[k][m]
    __shared__ float Bs[GBK][HD];    // Bs[k][n]

    const int which = blockIdx.y;
    const float* W; const float* bias; float* out;
    if (which == 0)      { W = Wq; bias = Bq; out = g_Q; }
    else if (which == 1) { W = Wk; bias = Bk; out = g_K; }
    else                 { W = Wv; bias = Bv; out = g_V; }
    const bool rope = (which < 2);

    const int tid = threadIdx.x;
    const int tx = tid & 15;     // column group
    const int ty = tid >> 4;     // row group
    const int m0 = blockIdx.x * GBM;

    // Prefetch registers (2 float4 each for A and B per thread)
    float4 pa[2], pb[2];
    #pragma unroll
    for (int t = 0; t < 2; t++) {
        int idx = tid + t * 256;
        int arow = idx >> 2, acol = (idx & 3) * 4;
        pa[t] = *(const float4*)&x[(size_t)(m0 + arow) * EMB + acol];
        int brow = idx >> 5, bcol = (idx & 31) * 4;
        pb[t] = *(const float4*)&W[brow * HD + bcol];
    }

    float acc[8][8];
    #pragma unroll
    for (int i = 0; i < 8; i++)
        #pragma unroll
        for (int j = 0; j < 8; j++) acc[i][j] = 0.f;

    for (int k0 = 0; k0 < EMB; k0 += GBK) {
        // Commit prefetched tile to smem
        #pragma unroll
        for (int t = 0; t < 2; t++) {
            int idx = tid + t * 256;
            int arow = idx >> 2, acol = (idx & 3) * 4;
            As[acol+0][arow] = pa[t].x;
            As[acol+1][arow] = pa[t].y;
            As[acol+2][arow] = pa[t].z;
            As[acol+3][arow] = pa[t].w;
            int brow = idx >> 5, bcol = (idx & 31) * 4;
            *(float4*)&Bs[brow][bcol] = pb[t];
        }
        __syncthreads();

        // Prefetch next tile (gmem latency hidden behind compute)
        if (k0 + GBK < EMB) {
            int kn = k0 + GBK;
            #pragma unroll
            for (int t = 0; t < 2; t++) {
                int idx = tid + t * 256;
                int arow = idx >> 2, acol = (idx & 3) * 4;
                pa[t] = *(const float4*)&x[(size_t)(m0 + arow) * EMB + kn + acol];
                int brow = idx >> 5, bcol = (idx & 31) * 4;
                pb[t] = *(const float4*)&W[(kn + brow) * HD + bcol];
            }
        }

        #pragma unroll 8
        for (int k = 0; k < GBK; k++) {
            float4 a0 = *(const float4*)&As[k][ty*4];
            float4 a1 = *(const float4*)&As[k][ty*4 + 64];
            float4 b0 = *(const float4*)&Bs[k][tx*4];
            float4 b1 = *(const float4*)&Bs[k][tx*4 + 64];
            float ar[8] = {a0.x,a0.y,a0.z,a0.w,a1.x,a1.y,a1.z,a1.w};
            float br[8] = {b0.x,b0.y,b0.z,b0.w,b1.x,b1.y,b1.z,b1.w};
            #pragma unroll
            for (int i = 0; i < 8; i++)
                #pragma unroll
                for (int j = 0; j < 8; j++)
                    acc[i][j] += ar[i] * br[j];
        }
        __syncthreads();
    }

    // Epilogue: bias + RoPE (+write). Thread's 4-aligned column chunks keep
    // rotation pairs (2i, 2i+1) in-thread.
    float bvals[8];
    #pragma unroll
    for (int j = 0; j < 8; j++) {
        int c = (j < 4) ? (tx*4 + j) : (64 + tx*4 + (j - 4));
        bvals[j] = bias[c];
    }
    #pragma unroll
    for (int i = 0; i < 8; i++) {
        int row  = m0 + ty*4 + (i & 3) + ((i >> 2) * 64);
        int spos = row & (SEQ - 1);
        float* orow = out + (size_t)row * HD;
        #pragma unroll
        for (int jp = 0; jp < 4; jp++) {
            int j = jp * 2;
            int c = (j < 4) ? (tx*4 + j) : (64 + tx*4 + (j - 4));
            float a = acc[i][j]   + bvals[j];
            float b = acc[i][j+1] + bvals[j+1];
            if (rope) {
                float cs = g_cos[spos*64 + (c >> 1)];
                float sn = g_sin[spos*64 + (c >> 1)];
                orow[c]   = a*cs - b*sn;
                orow[c+1] = b*cs + a*sn;
            } else {
                orow[c]   = a;
                orow[c+1] = b;
            }
        }
    }
}

// ---------------------------------------------------------------------------
// Flash attention (causal), BM=BN=64, D=128, 256 threads, fp32.
// Qt/Kt stored [d][64] (float4 LDS for both S-GEMM operands),
// Ps stored [k][m], Vs [k][d] (float4 LDS for PV).
// ---------------------------------------------------------------------------
#define ATT_SMEM_FLOATS (128*64 + 128*64 + 64*128 + 64*64 + 64*3)
#define ATT_SMEM_BYTES  (ATT_SMEM_FLOATS * 4)

__global__ __launch_bounds__(256, 2) void attn_kernel(float* __restrict__ out)
{
    extern __shared__ float sm[];
    float* Qt  = sm;                 // [128][64]
    float* Kt  = Qt + 128*64;        // [128][64]
    float* Vs  = Kt + 128*64;        // [64][128]
    float* Ps  = Vs + 64*128;        // [64][64]  (key-major)
    float* m_s = Ps + 64*64;         // [64] running max
    float* l_s = m_s + 64;           // [64] running sumexp
    float* al_s= l_s + 64;           // [64] rescale factor

    const int tid = threadIdx.x;
    const int bx  = blockIdx.x;
    const int b   = blockIdx.y;
    const int m_start = bx * 64;

    const float* Qg = g_Q + (size_t)b * SEQ * HD;
    const float* Kg = g_K + (size_t)b * SEQ * HD;
    const float* Vg = g_V + (size_t)b * SEQ * HD;

    // Load Q tile transposed: lane varies m (conflict-free smem stores)
    #pragma unroll
    for (int t = 0; t < 8; t++) {
        int idx = tid + t * 256;
        int m = idx & 63;
        int d = (idx >> 6) * 4;
        float4 v = *(const float4*)&Qg[(size_t)(m_start + m) * HD + d];
        Qt[(d+0)*64 + m] = v.x;
        Qt[(d+1)*64 + m] = v.y;
        Qt[(d+2)*64 + m] = v.z;
        Qt[(d+3)*64 + m] = v.w;
    }
    if (tid < 64) { m_s[tid] = -INFINITY; l_s[tid] = 0.f; }

    float o[4][8];
    #pragma unroll
    for (int i = 0; i < 4; i++)
        #pragma unroll
        for (int c = 0; c < 8; c++) o[i][c] = 0.f;

    const int r0S = (tid & 15) * 4;   // S-gemm rows
    const int n0S = (tid >> 4) * 4;   // S-gemm keys
    const int r0P = (tid & 15) * 4;   // PV rows
    const int c0P = (tid >> 4) * 8;   // PV cols
    const int srow = tid >> 2;        // softmax row
    const int sq   = tid & 3;         // softmax quad lane
    const float scale = 0.08838834764831845f;  // 1/sqrt(128)

    for (int j = 0; j <= bx; j++) {
        __syncthreads();   // previous tile's consumers done (also covers Q load / stat init)
        const int nb = j * 64;

        // K tile transposed
        #pragma unroll
        for (int t = 0; t < 8; t++) {
            int idx = tid + t * 256;
            int m = idx & 63;
            int d = (idx >> 6) * 4;
            float4 v = *(const float4*)&Kg[(size_t)(nb + m) * HD + d];
            Kt[(d+0)*64 + m] = v.x;
            Kt[(d+1)*64 + m] = v.y;
            Kt[(d+2)*64 + m] = v.z;
            Kt[(d+3)*64 + m] = v.w;
        }
        // V tile row-major
        #pragma unroll
        for (int t = 0; t < 8; t++) {
            int idx = tid + t * 256;
            int m = idx >> 5;
            int d = (idx & 31) * 4;
            *(float4*)&Vs[m*128 + d] = *(const float4*)&Vg[(size_t)(nb + m) * HD + d];
        }
        __syncthreads();

        // S = Q K^T (4x4 per thread)
        float s[4][4];
        #pragma unroll
        for (int i = 0; i < 4; i++)
            #pragma unroll
            for (int jj = 0; jj < 4; jj++) s[i][jj] = 0.f;
        #pragma unroll 8
        for (int d = 0; d < 128; d++) {
            float4 q  = *(const float4*)&Qt[d*64 + r0S];
            float4 kk = *(const float4*)&Kt[d*64 + n0S];
            float qa[4] = {q.x, q.y, q.z, q.w};
            float ka[4] = {kk.x, kk.y, kk.z, kk.w};
            #pragma unroll
            for (int i = 0; i < 4; i++)
                #pragma unroll
                for (int jj = 0; jj < 4; jj++)
                    s[i][jj] += qa[i] * ka[jj];
        }
        const bool diag = (j == bx);
        #pragma unroll
        for (int i = 0; i < 4; i++)
            #pragma unroll
            for (int jj = 0; jj < 4; jj++) {
                float v = s[i][jj] * scale;
                if (diag && (n0S + jj > r0S + i)) v = -1e30f;
                Ps[(n0S + jj)*64 + (r0S + i)] = v;
            }
        __syncthreads();

        // Online softmax: 4 threads per row, quad shuffle reduce
        float vals[16];
        float mx = -INFINITY;
        #pragma unroll
        for (int i = 0; i < 16; i++) {
            vals[i] = Ps[(sq*16 + i)*64 + srow];
            mx = fmaxf(mx, vals[i]);
        }
        mx = fmaxf(mx, __shfl_xor_sync(0xffffffffu, mx, 1));
        mx = fmaxf(mx, __shfl_xor_sync(0xffffffffu, mx, 2));
        float mprev = m_s[srow];
        float mnew  = fmaxf(mprev, mx);
        float sum = 0.f;
        #pragma unroll
        for (int i = 0; i < 16; i++) {
            float p = __expf(vals[i] - mnew);
            Ps[(sq*16 + i)*64 + srow] = p;
            sum += p;
        }
        sum += __shfl_xor_sync(0xffffffffu, sum, 1);
        sum += __shfl_xor_sync(0xffffffffu, sum, 2);
        if (sq == 0) {
            float alpha = __expf(mprev - mnew);
            al_s[srow] = alpha;
            l_s[srow]  = l_s[srow] * alpha + sum;
            m_s[srow]  = mnew;
        }
        __syncthreads();

        // O = O*alpha + P @ V (4 rows x 8 cols per thread)
        float al[4];
        #pragma unroll
        for (int i = 0; i < 4; i++) al[i] = al_s[r0P + i];
        #pragma unroll
        for (int i = 0; i < 4; i++)
            #pragma unroll
            for (int c = 0; c < 8; c++) o[i][c] *= al[i];
        #pragma unroll 4
        for (int k = 0; k < 64; k++) {
            float4 p  = *(const float4*)&Ps[k*64  + r0P];
            float4 v0 = *(const float4*)&Vs[k*128 + c0P];
            float4 v1 = *(const float4*)&Vs[k*128 + c0P + 4];
            float pa[4] = {p.x, p.y, p.z, p.w};
            float va[8] = {v0.x, v0.y, v0.z, v0.w, v1.x, v1.y, v1.z, v1.w};
            #pragma unroll
            for (int i = 0; i < 4; i++)
                #pragma unroll
                for (int c = 0; c < 8; c++)
                    o[i][c] += pa[i] * va[c];
        }
    }

    // Normalize and write
    #pragma unroll
    for (int i = 0; i < 4; i++) {
        float inv = 1.0f / l_s[r0P + i];
        int row = m_start + r0P + i;
        float* orow = out + ((size_t)b * SEQ + row) * HD;
        float4 w0 = make_float4(o[i][0]*inv, o[i][1]*inv, o[i][2]*inv, o[i][3]*inv);
        float4 w1 = make_float4(o[i][4]*inv, o[i][5]*inv, o[i][6]*inv, o[i][7]*inv);
        *(float4*)&orow[c0P]     = w0;
        *(float4*)&orow[c0P + 4] = w1;
    }
}

// ---------------------------------------------------------------------------
extern "C" void kernel_launch(void* const* d_in, const int* in_sizes, int n_in,
                              void* d_out, int out_size)
{
    const float* x  = (const float*)d_in[0];
    const float* Wq = (const float*)d_in[1];
    const float* bq = (const float*)d_in[2];
    const float* Wk = (const float*)d_in[3];
    const float* bk = (const float*)d_in[4];
    const float* Wv = (const float*)d_in[5];
    const float* bv = (const float*)d_in[6];
    float* out = (float*)d_out;

    rope_table_kernel<<<(SEQ*(HD/2) + 255)/256, 256>>>();

    dim3 g1(MTOT / GBM, 3);
    qkv_gemm_kernel<<<g1, 256>>>(x, Wq, bq, Wk, bk, Wv, bv);

    cudaFuncSetAttribute(attn_kernel,
                         cudaFuncAttributeMaxDynamicSharedMemorySize,
                         ATT_SMEM_BYTES);
    dim3 g2(SEQ / 64, BATCH);
    attn_kernel<<<g2, 256, ATT_SMEM_BYTES>>>(out);
}

// round 4
// speedup vs baseline: 1.2388x; 1.2388x over previous
#include <cuda_runtime.h>
#include <cuda_bf16.h>
#include <math.h>
#include <stdint.h>

#define BATCH 4
#define SEQ   4096
#define EMB   2048
#define HD    128
#define MTOT  (BATCH*SEQ)

// ---------------------------------------------------------------------------
// Device-global scratch (no allocation allowed)
// ---------------------------------------------------------------------------
static __device__ float g_Q[MTOT*HD];
static __device__ float g_K[MTOT*HD];
static __device__ float g_V[MTOT*HD];
static __device__ float g_cos[SEQ*(HD/2)];
static __device__ float g_sin[SEQ*(HD/2)];
static __device__ __nv_bfloat16 g_xhi[(size_t)MTOT*EMB];
static __device__ __nv_bfloat16 g_xlo[(size_t)MTOT*EMB];
static __device__ __nv_bfloat16 g_wthi[3*HD*EMB];   // [mat][n][k]
static __device__ __nv_bfloat16 g_wtlo[3*HD*EMB];

// ---------------------------------------------------------------------------
// PTX helpers: cp.async + ldmatrix + mma.sync (all valid on compute_100)
// ---------------------------------------------------------------------------
__device__ __forceinline__ uint32_t smem_u32(const void* p) {
    uint32_t a;
    asm("{ .reg .u64 t; cvta.to.shared.u64 t, %1; cvt.u32.u64 %0, t; }" : "=r"(a) : "l"(p));
    return a;
}

#define SW128(off) ((off) ^ (((off) >> 3) & 0x70))

__device__ __forceinline__ void cpasync16(uint32_t dst, const void* src) {
    asm volatile("cp.async.cg.shared.global [%0], [%1], 16;" :: "r"(dst), "l"(src) : "memory");
}
#define CP_COMMIT()  asm volatile("cp.async.commit_group;" ::: "memory")
#define CP_WAIT2()   asm volatile("cp.async.wait_group 2;" ::: "memory")

__device__ __forceinline__ void ldsm4(uint32_t r[4], uint32_t addr) {
    asm volatile("ldmatrix.sync.aligned.m8n8.x4.shared.b16 {%0,%1,%2,%3}, [%4];"
                 : "=r"(r[0]), "=r"(r[1]), "=r"(r[2]), "=r"(r[3]) : "r"(addr));
}

__device__ __forceinline__ void mma16816(float c[4],
                                         const uint32_t a[4],
                                         uint32_t b0, uint32_t b1) {
    asm volatile(
        "mma.sync.aligned.m16n8k16.row.col.f32.bf16.bf16.f32 "
        "{%0,%1,%2,%3}, {%4,%5,%6,%7}, {%8,%9}, {%0,%1,%2,%3};"
        : "+f"(c[0]), "+f"(c[1]), "+f"(c[2]), "+f"(c[3])
        : "r"(a[0]), "r"(a[1]), "r"(a[2]), "r"(a[3]), "r"(b0), "r"(b1));
}

// ---------------------------------------------------------------------------
// RoPE tables
// ---------------------------------------------------------------------------
__global__ void rope_table_kernel() {
    int idx = blockIdx.x * blockDim.x + threadIdx.x;
    if (idx >= SEQ * (HD/2)) return;
    int s = idx >> 6;
    int i = idx & 63;
    double freqd = exp(-(double)(2*i) * (9.210340371976184 / 128.0));
    float angle = (float)s * (float)freqd;
    float sn, cs;
    sincosf(angle, &sn, &cs);
    g_cos[idx] = cs;
    g_sin[idx] = sn;
}

// ---------------------------------------------------------------------------
// bf16 2-term splits
// ---------------------------------------------------------------------------
__global__ void split_x_kernel(const float* __restrict__ x) {
    size_t idx = (size_t)blockIdx.x * blockDim.x + threadIdx.x;   // per float4
    if (idx >= (size_t)MTOT * EMB / 4) return;
    float4 v = ((const float4*)x)[idx];
    __nv_bfloat16 h0 = __float2bfloat16(v.x);
    __nv_bfloat16 h1 = __float2bfloat16(v.y);
    __nv_bfloat16 h2 = __float2bfloat16(v.z);
    __nv_bfloat16 h3 = __float2bfloat16(v.w);
    __nv_bfloat16 l0 = __float2bfloat16(v.x - __bfloat162float(h0));
    __nv_bfloat16 l1 = __float2bfloat16(v.y - __bfloat162float(h1));
    __nv_bfloat16 l2 = __float2bfloat16(v.z - __bfloat162float(h2));
    __nv_bfloat16 l3 = __float2bfloat16(v.w - __bfloat162float(h3));
    ((__nv_bfloat162*)g_xhi)[2*idx]   = __nv_bfloat162(h0, h1);
    ((__nv_bfloat162*)g_xhi)[2*idx+1] = __nv_bfloat162(h2, h3);
    ((__nv_bfloat162*)g_xlo)[2*idx]   = __nv_bfloat162(l0, l1);
    ((__nv_bfloat162*)g_xlo)[2*idx+1] = __nv_bfloat162(l2, l3);
}

__global__ void split_w_kernel(const float* __restrict__ Wq,
                               const float* __restrict__ Wk,
                               const float* __restrict__ Wv) {
    int idx = blockIdx.x * blockDim.x + threadIdx.x;   // 3*EMB*HD
    if (idx >= 3 * EMB * HD) return;
    int mat = idx / (EMB * HD);
    int r   = idx % (EMB * HD);
    int k = r / HD, n = r % HD;
    const float* W = (mat == 0) ? Wq : (mat == 1) ? Wk : Wv;
    float v = W[r];
    __nv_bfloat16 hi = __float2bfloat16(v);
    __nv_bfloat16 lo = __float2bfloat16(v - __bfloat162float(hi));
    g_wthi[(size_t)mat*HD*EMB + (size_t)n*EMB + k] = hi;
    g_wtlo[(size_t)mat*HD*EMB + (size_t)n*EMB + k] = lo;
}

// ---------------------------------------------------------------------------
// QKV projection via warp-level mma.sync (bf16 split, fp32 accum).
// CTA tile 128x128, Kc=64, 3-stage cp.async pipeline, 8 warps (4x2 m x n).
// grid (3 matrices, 128 m-tiles) -> consecutive CTAs share A tile via L2.
// ---------------------------------------------------------------------------
#define KC       64
#define NCHUNK   (EMB / KC)          // 32
#define TILE_B   16384               // 128 rows x 128 bytes
#define STAGE_B  (4 * TILE_B)        // Ahi, Alo, Bhi, Blo
#define QKV_SMEM (1024 + 3 * STAGE_B)

__global__ __launch_bounds__(256, 1) void qkv_mma_kernel(
    const float* __restrict__ Bq, const float* __restrict__ Bk,
    const float* __restrict__ Bv)
{
    extern __shared__ char smem_raw[];
    uint32_t base = (smem_u32(smem_raw) + 1023) & ~1023u;   // 1KB align (SW128)
    const int tid  = threadIdx.x;
    const int wid  = tid >> 5;
    const int lane = tid & 31;
    const int mat  = blockIdx.x;
    const int m0   = blockIdx.y * 128;

    const __nv_bfloat16* Ahi = g_xhi + (size_t)m0 * EMB;
    const __nv_bfloat16* Alo = g_xlo + (size_t)m0 * EMB;
    const __nv_bfloat16* Bhi = g_wthi + (size_t)mat * HD * EMB;
    const __nv_bfloat16* Blo = g_wtlo + (size_t)mat * HD * EMB;
    const float* bias = (mat == 0) ? Bq : (mat == 1) ? Bk : Bv;
    float* out = (mat == 0) ? g_Q : (mat == 1) ? g_K : g_V;

    const int wm = wid & 3;       // m quadrant (32 rows)
    const int wn = wid >> 2;      // n half (64 cols)

    // ldmatrix lane decomposition (x4): lanes 0-7 -> mat0, 8-15 -> mat1, etc.
    const int lr     = lane & 7;
    const int sel    = lane >> 3;
    const int rowadd = (sel & 1) * 8;
    const int kselb  = (sel >> 1) * 16;

    float acc[2][8][4];
    #pragma unroll
    for (int i = 0; i < 2; i++)
        #pragma unroll
        for (int j = 0; j < 8; j++)
            #pragma unroll
            for (int c = 0; c < 4; c++) acc[i][j][c] = 0.f;

    // cp.async producer slice: 4 x 16B per operand tile per thread
    auto load_chunk = [&](int chunk, int s) {
        const int k0 = chunk * KC;
        const uint32_t st = base + s * STAGE_B;
        #pragma unroll
        for (int t = 0; t < 4; t++) {
            int idx = tid + t * 256;
            int row = idx >> 3;
            int c16 = idx & 7;
            uint32_t off = SW128((uint32_t)(row * 128 + c16 * 16));
            const size_t g = (size_t)row * EMB + k0 + c16 * 8;
            cpasync16(st + 0*TILE_B + off, Ahi + g);
            cpasync16(st + 1*TILE_B + off, Alo + g);
            cpasync16(st + 2*TILE_B + off, Bhi + g);
            cpasync16(st + 3*TILE_B + off, Blo + g);
        }
    };

    load_chunk(0, 0); CP_COMMIT();
    load_chunk(1, 1); CP_COMMIT();
    load_chunk(2, 2); CP_COMMIT();

    for (int i = 0; i < NCHUNK; i++) {
        const int s = i - (i / 3) * 3;
        CP_WAIT2();
        __syncthreads();

        const uint32_t st   = base + s * STAGE_B;
        const uint32_t aHiB = st;
        const uint32_t aLoB = st + TILE_B;
        const uint32_t bHiB = st + 2*TILE_B;
        const uint32_t bLoB = st + 3*TILE_B;

        #pragma unroll
        for (int kk = 0; kk < 4; kk++) {
            const int kb = kk * 32;

            uint32_t ahi[2][4], alo[2][4];
            #pragma unroll
            for (int f = 0; f < 2; f++) {
                int row = wm*32 + f*16 + rowadd + lr;
                uint32_t byte = (uint32_t)(kb + kselb) ^ (uint32_t)((row & 7) * 16);
                uint32_t off  = (uint32_t)row * 128 + byte;
                ldsm4(ahi[f], aHiB + off);
                ldsm4(alo[f], aLoB + off);
            }
            uint32_t bhi[8][2], blo[8][2];
            #pragma unroll
            for (int jj = 0; jj < 4; jj++) {
                int row = wn*64 + jj*16 + rowadd + lr;
                uint32_t byte = (uint32_t)(kb + kselb) ^ (uint32_t)((row & 7) * 16);
                uint32_t off  = (uint32_t)row * 128 + byte;
                uint32_t t[4];
                ldsm4(t, bHiB + off);
                bhi[2*jj][0]   = t[0]; bhi[2*jj][1]   = t[2];
                bhi[2*jj+1][0] = t[1]; bhi[2*jj+1][1] = t[3];
                ldsm4(t, bLoB + off);
                blo[2*jj][0]   = t[0]; blo[2*jj][1]   = t[2];
                blo[2*jj+1][0] = t[1]; blo[2*jj+1][1] = t[3];
            }
            #pragma unroll
            for (int f = 0; f < 2; f++)
                #pragma unroll
                for (int j = 0; j < 8; j++) {
                    mma16816(acc[f][j], ahi[f], bhi[j][0], bhi[j][1]);
                    mma16816(acc[f][j], ahi[f], blo[j][0], blo[j][1]);
                    mma16816(acc[f][j], alo[f], bhi[j][0], bhi[j][1]);
                }
        }

        __syncthreads();
        if (i + 3 < NCHUNK) load_chunk(i + 3, s);
        CP_COMMIT();
    }

    // Epilogue: bias + RoPE, float2 stores. C frag: rows lane>>2 (+8), cols
    // (lane&3)*2,+1 -> rotation pairs in-thread.
    const bool rope = (mat < 2);
    #pragma unroll
    for (int f = 0; f < 2; f++) {
        #pragma unroll
        for (int j = 0; j < 8; j++) {
            int c = wn*64 + j*8 + (lane & 3)*2;
            float b0 = bias[c], b1 = bias[c + 1];
            #pragma unroll
            for (int h = 0; h < 2; h++) {
                int row  = m0 + wm*32 + f*16 + (lane >> 2) + h*8;
                int spos = row & (SEQ - 1);
                float a = acc[f][j][2*h]     + b0;
                float b = acc[f][j][2*h + 1] + b1;
                float* orow = out + (size_t)row * HD;
                if (rope) {
                    float cs = g_cos[spos*64 + (c >> 1)];
                    float sn = g_sin[spos*64 + (c >> 1)];
                    *(float2*)&orow[c] = make_float2(a*cs - b*sn, b*cs + a*sn);
                } else {
                    *(float2*)&orow[c] = make_float2(a, b);
                }
            }
        }
    }
}

// ---------------------------------------------------------------------------
// Flash attention (causal), fp32, unchanged (passing baseline).
// ---------------------------------------------------------------------------
#define ATT_SMEM_FLOATS (128*64 + 128*64 + 64*128 + 64*64 + 64*3)
#define ATT_SMEM_BYTES  (ATT_SMEM_FLOATS * 4)

__global__ __launch_bounds__(256, 2) void attn_kernel(float* __restrict__ out)
{
    extern __shared__ float sm[];
    float* Qt  = sm;
    float* Kt  = Qt + 128*64;
    float* Vs  = Kt + 128*64;
    float* Ps  = Vs + 64*128;
    float* m_s = Ps + 64*64;
    float* l_s = m_s + 64;
    float* al_s= l_s + 64;

    const int tid = threadIdx.x;
    const int bx  = blockIdx.x;
    const int b   = blockIdx.y;
    const int m_start = bx * 64;

    const float* Qg = g_Q + (size_t)b * SEQ * HD;
    const float* Kg = g_K + (size_t)b * SEQ * HD;
    const float* Vg = g_V + (size_t)b * SEQ * HD;

    #pragma unroll
    for (int t = 0; t < 8; t++) {
        int idx = tid + t * 256;
        int m = idx & 63;
        int d = (idx >> 6) * 4;
        float4 v = *(const float4*)&Qg[(size_t)(m_start + m) * HD + d];
        Qt[(d+0)*64 + m] = v.x;
        Qt[(d+1)*64 + m] = v.y;
        Qt[(d+2)*64 + m] = v.z;
        Qt[(d+3)*64 + m] = v.w;
    }
    if (tid < 64) { m_s[tid] = -INFINITY; l_s[tid] = 0.f; }

    float o[4][8];
    #pragma unroll
    for (int i = 0; i < 4; i++)
        #pragma unroll
        for (int c = 0; c < 8; c++) o[i][c] = 0.f;

    const int r0S = (tid & 15) * 4;
    const int n0S = (tid >> 4) * 4;
    const int r0P = (tid & 15) * 4;
    const int c0P = (tid >> 4) * 8;
    const int srow = tid >> 2;
    const int sq   = tid & 3;
    const float scale = 0.08838834764831845f;

    for (int j = 0; j <= bx; j++) {
        __syncthreads();
        const int nb = j * 64;

        #pragma unroll
        for (int t = 0; t < 8; t++) {
            int idx = tid + t * 256;
            int m = idx & 63;
            int d = (idx >> 6) * 4;
            float4 v = *(const float4*)&Kg[(size_t)(nb + m) * HD + d];
            Kt[(d+0)*64 + m] = v.x;
            Kt[(d+1)*64 + m] = v.y;
            Kt[(d+2)*64 + m] = v.z;
            Kt[(d+3)*64 + m] = v.w;
        }
        #pragma unroll
        for (int t = 0; t < 8; t++) {
            int idx = tid + t * 256;
            int m = idx >> 5;
            int d = (idx & 31) * 4;
            *(float4*)&Vs[m*128 + d] = *(const float4*)&Vg[(size_t)(nb + m) * HD + d];
        }
        __syncthreads();

        float s[4][4];
        #pragma unroll
        for (int i = 0; i < 4; i++)
            #pragma unroll
            for (int jj = 0; jj < 4; jj++) s[i][jj] = 0.f;
        #pragma unroll 8
        for (int d = 0; d < 128; d++) {
            float4 q  = *(const float4*)&Qt[d*64 + r0S];
            float4 kk = *(const float4*)&Kt[d*64 + n0S];
            float qa[4] = {q.x, q.y, q.z, q.w};
            float ka[4] = {kk.x, kk.y, kk.z, kk.w};
            #pragma unroll
            for (int i = 0; i < 4; i++)
                #pragma unroll
                for (int jj = 0; jj < 4; jj++)
                    s[i][jj] += qa[i] * ka[jj];
        }
        const bool diag = (j == bx);
        #pragma unroll
        for (int i = 0; i < 4; i++)
            #pragma unroll
            for (int jj = 0; jj < 4; jj++) {
                float v = s[i][jj] * scale;
                if (diag && (n0S + jj > r0S + i)) v = -1e30f;
                Ps[(n0S + jj)*64 + (r0S + i)] = v;
            }
        __syncthreads();

        float vals[16];
        float mx = -INFINITY;
        #pragma unroll
        for (int i = 0; i < 16; i++) {
            vals[i] = Ps[(sq*16 + i)*64 + srow];
            mx = fmaxf(mx, vals[i]);
        }
        mx = fmaxf(mx, __shfl_xor_sync(0xffffffffu, mx, 1));
        mx = fmaxf(mx, __shfl_xor_sync(0xffffffffu, mx, 2));
        float mprev = m_s[srow];
        float mnew  = fmaxf(mprev, mx);
        float sum = 0.f;
        #pragma unroll
        for (int i = 0; i < 16; i++) {
            float p = __expf(vals[i] - mnew);
            Ps[(sq*16 + i)*64 + srow] = p;
            sum += p;
        }
        sum += __shfl_xor_sync(0xffffffffu, sum, 1);
        sum += __shfl_xor_sync(0xffffffffu, sum, 2);
        if (sq == 0) {
            float alpha = __expf(mprev - mnew);
            al_s[srow] = alpha;
            l_s[srow]  = l_s[srow] * alpha + sum;
            m_s[srow]  = mnew;
        }
        __syncthreads();

        float al[4];
        #pragma unroll
        for (int i = 0; i < 4; i++) al[i] = al_s[r0P + i];
        #pragma unroll
        for (int i = 0; i < 4; i++)
            #pragma unroll
            for (int c = 0; c < 8; c++) o[i][c] *= al[i];
        #pragma unroll 4
        for (int k = 0; k < 64; k++) {
            float4 p  = *(const float4*)&Ps[k*64  + r0P];
            float4 v0 = *(const float4*)&Vs[k*128 + c0P];
            float4 v1 = *(const float4*)&Vs[k*128 + c0P + 4];
            float pa[4] = {p.x, p.y, p.z, p.w};
            float va[8] = {v0.x, v0.y, v0.z, v0.w, v1.x, v1.y, v1.z, v1.w};
            #pragma unroll
            for (int i = 0; i < 4; i++)
                #pragma unroll
                for (int c = 0; c < 8; c++)
                    o[i][c] += pa[i] * va[c];
        }
    }

    #pragma unroll
    for (int i = 0; i < 4; i++) {
        float inv = 1.0f / l_s[r0P + i];
        int row = m_start + r0P + i;
        float* orow = out + ((size_t)b * SEQ + row) * HD;
        float4 w0 = make_float4(o[i][0]*inv, o[i][1]*inv, o[i][2]*inv, o[i][3]*inv);
        float4 w1 = make_float4(o[i][4]*inv, o[i][5]*inv, o[i][6]*inv, o[i][7]*inv);
        *(float4*)&orow[c0P]     = w0;
        *(float4*)&orow[c0P + 4] = w1;
    }
}

// ---------------------------------------------------------------------------
extern "C" void kernel_launch(void* const* d_in, const int* in_sizes, int n_in,
                              void* d_out, int out_size)
{
    const float* x  = (const float*)d_in[0];
    const float* Wq = (const float*)d_in[1];
    const float* bq = (const float*)d_in[2];
    const float* Wk = (const float*)d_in[3];
    const float* bk = (const float*)d_in[4];
    const float* Wv = (const float*)d_in[5];
    const float* bv = (const float*)d_in[6];
    float* out = (float*)d_out;

    rope_table_kernel<<<(SEQ*(HD/2) + 255)/256, 256>>>();
    split_x_kernel<<<(MTOT*(EMB/4) + 255)/256, 256>>>(x);
    split_w_kernel<<<(3*EMB*HD + 255)/256, 256>>>(Wq, Wk, Wv);

    cudaFuncSetAttribute(qkv_mma_kernel,
                         cudaFuncAttributeMaxDynamicSharedMemorySize, QKV_SMEM);
    dim3 g1(3, MTOT / 128);
    qkv_mma_kernel<<<g1, 256, QKV_SMEM>>>(bq, bk, bv);

    cudaFuncSetAttribute(attn_kernel,
                         cudaFuncAttributeMaxDynamicSharedMemorySize, ATT_SMEM_BYTES);
    dim3 g2(SEQ / 64, BATCH);
    attn_kernel<<<g2, 256, ATT_SMEM_BYTES>>>(out);
}

// round 7
// speedup vs baseline: 2.8737x; 2.3197x over previous
#include <cuda_runtime.h>
#include <cuda_bf16.h>
#include <math.h>
#include <stdint.h>

#define BATCH 4
#define SEQ   4096
#define EMB   2048
#define HD    128
#define MTOT  (BATCH*SEQ)

// ---------------------------------------------------------------------------
// Device-global scratch (no allocation allowed)
// ---------------------------------------------------------------------------
static __device__ float g_cos[SEQ*(HD/2)];
static __device__ float g_sin[SEQ*(HD/2)];
static __device__ __nv_bfloat16 g_xhi[(size_t)MTOT*EMB];
static __device__ __nv_bfloat16 g_xlo[(size_t)MTOT*EMB];
static __device__ __nv_bfloat16 g_wthi[3*HD*EMB];   // [mat][n][k]
static __device__ __nv_bfloat16 g_wtlo[3*HD*EMB];
// attention operands (bf16 2-term splits, written by QKV epilogue)
static __device__ __nv_bfloat16 g_Qhi[(size_t)MTOT*HD];   // [b*s][d]
static __device__ __nv_bfloat16 g_Qlo[(size_t)MTOT*HD];
static __device__ __nv_bfloat16 g_Khi[(size_t)MTOT*HD];
static __device__ __nv_bfloat16 g_Klo[(size_t)MTOT*HD];
static __device__ __nv_bfloat16 g_Vthi[(size_t)MTOT*HD];  // [b][d][s]
static __device__ __nv_bfloat16 g_Vtlo[(size_t)MTOT*HD];

// ---------------------------------------------------------------------------
// PTX helpers
// ---------------------------------------------------------------------------
__device__ __forceinline__ uint32_t smem_u32(const void* p) {
    uint32_t a;
    asm("{ .reg .u64 t; cvta.to.shared.u64 t, %1; cvt.u32.u64 %0, t; }" : "=r"(a) : "l"(p));
    return a;
}

#define SW128(off) ((off) ^ (((off) >> 3) & 0x70))

__device__ __forceinline__ void cpasync16(uint32_t dst, const void* src) {
    asm volatile("cp.async.cg.shared.global [%0], [%1], 16;" :: "r"(dst), "l"(src) : "memory");
}
#define CP_COMMIT()  asm volatile("cp.async.commit_group;" ::: "memory")
#define CP_WAIT2()   asm volatile("cp.async.wait_group 2;" ::: "memory")
#define CP_WAIT0()   asm volatile("cp.async.wait_group 0;" ::: "memory")

__device__ __forceinline__ void ldsm4(uint32_t r[4], uint32_t addr) {
    asm volatile("ldmatrix.sync.aligned.m8n8.x4.shared.b16 {%0,%1,%2,%3}, [%4];"
                 : "=r"(r[0]), "=r"(r[1]), "=r"(r[2]), "=r"(r[3]) : "r"(addr));
}

__device__ __forceinline__ void mma16816(float c[4],
                                         const uint32_t a[4],
                                         uint32_t b0, uint32_t b1) {
    asm volatile(
        "mma.sync.aligned.m16n8k16.row.col.f32.bf16.bf16.f32 "
        "{%0,%1,%2,%3}, {%4,%5,%6,%7}, {%8,%9}, {%0,%1,%2,%3};"
        : "+f"(c[0]), "+f"(c[1]), "+f"(c[2]), "+f"(c[3])
        : "r"(a[0]), "r"(a[1]), "r"(a[2]), "r"(a[3]), "r"(b0), "r"(b1));
}

__device__ __forceinline__ void split_pack(float va, float vb,
                                           uint32_t& hi, uint32_t& lo) {
    __nv_bfloat16 ha = __float2bfloat16(va), hb = __float2bfloat16(vb);
    __nv_bfloat162 H(ha, hb);
    hi = *(uint32_t*)&H;
    __nv_bfloat162 L(__float2bfloat16(va - __bfloat162float(ha)),
                     __float2bfloat16(vb - __bfloat162float(hb)));
    lo = *(uint32_t*)&L;
}

// ---------------------------------------------------------------------------
// RoPE tables
// ---------------------------------------------------------------------------
__global__ void rope_table_kernel() {
    int idx = blockIdx.x * blockDim.x + threadIdx.x;
    if (idx >= SEQ * (HD/2)) return;
    int s = idx >> 6;
    int i = idx & 63;
    double freqd = exp(-(double)(2*i) * (9.210340371976184 / 128.0));
    float angle = (float)s * (float)freqd;
    float sn, cs;
    sincosf(angle, &sn, &cs);
    g_cos[idx] = cs;
    g_sin[idx] = sn;
}

// ---------------------------------------------------------------------------
// bf16 2-term splits of inputs
// ---------------------------------------------------------------------------
__global__ void split_x_kernel(const float* __restrict__ x) {
    size_t idx = (size_t)blockIdx.x * blockDim.x + threadIdx.x;   // per float4
    if (idx >= (size_t)MTOT * EMB / 4) return;
    float4 v = ((const float4*)x)[idx];
    __nv_bfloat16 h0 = __float2bfloat16(v.x);
    __nv_bfloat16 h1 = __float2bfloat16(v.y);
    __nv_bfloat16 h2 = __float2bfloat16(v.z);
    __nv_bfloat16 h3 = __float2bfloat16(v.w);
    __nv_bfloat16 l0 = __float2bfloat16(v.x - __bfloat162float(h0));
    __nv_bfloat16 l1 = __float2bfloat16(v.y - __bfloat162float(h1));
    __nv_bfloat16 l2 = __float2bfloat16(v.z - __bfloat162float(h2));
    __nv_bfloat16 l3 = __float2bfloat16(v.w - __bfloat162float(h3));
    ((__nv_bfloat162*)g_xhi)[2*idx]   = __nv_bfloat162(h0, h1);
    ((__nv_bfloat162*)g_xhi)[2*idx+1] = __nv_bfloat162(h2, h3);
    ((__nv_bfloat162*)g_xlo)[2*idx]   = __nv_bfloat162(l0, l1);
    ((__nv_bfloat162*)g_xlo)[2*idx+1] = __nv_bfloat162(l2, l3);
}

__global__ void split_w_kernel(const float* __restrict__ Wq,
                               const float* __restrict__ Wk,
                               const float* __restrict__ Wv) {
    int idx = blockIdx.x * blockDim.x + threadIdx.x;   // 3*EMB*HD
    if (idx >= 3 * EMB * HD) return;
    int mat = idx / (EMB * HD);
    int r   = idx % (EMB * HD);
    int k = r / HD, n = r % HD;
    const float* W = (mat == 0) ? Wq : (mat == 1) ? Wk : Wv;
    float v = W[r];
    __nv_bfloat16 hi = __float2bfloat16(v);
    __nv_bfloat16 lo = __float2bfloat16(v - __bfloat162float(hi));
    g_wthi[(size_t)mat*HD*EMB + (size_t)n*EMB + k] = hi;
    g_wtlo[(size_t)mat*HD*EMB + (size_t)n*EMB + k] = lo;
}

// ---------------------------------------------------------------------------
// QKV projection via warp-level mma.sync (bf16 split, fp32 accum).
// Epilogue: bias + RoPE, then write bf16 hi/lo splits (V transposed [d][s]).
// ---------------------------------------------------------------------------
#define KC       64
#define NCHUNK   (EMB / KC)          // 32
#define TILE_B   16384               // 128 rows x 128 bytes
#define STAGE_B  (4 * TILE_B)        // Ahi, Alo, Bhi, Blo
#define QKV_SMEM (1024 + 3 * STAGE_B)

__global__ __launch_bounds__(256, 1) void qkv_mma_kernel(
    const float* __restrict__ Bq, const float* __restrict__ Bk,
    const float* __restrict__ Bv)
{
    extern __shared__ char smem_raw[];
    uint32_t base = (smem_u32(smem_raw) + 1023) & ~1023u;
    const int tid  = threadIdx.x;
    const int wid  = tid >> 5;
    const int lane = tid & 31;
    const int mat  = blockIdx.x;
    const int m0   = blockIdx.y * 128;

    const __nv_bfloat16* Ahi = g_xhi + (size_t)m0 * EMB;
    const __nv_bfloat16* Alo = g_xlo + (size_t)m0 * EMB;
    const __nv_bfloat16* Bhi = g_wthi + (size_t)mat * HD * EMB;
    const __nv_bfloat16* Blo = g_wtlo + (size_t)mat * HD * EMB;
    const float* bias = (mat == 0) ? Bq : (mat == 1) ? Bk : Bv;

    const int wm = wid & 3;
    const int wn = wid >> 2;

    const int lr     = lane & 7;
    const int sel    = lane >> 3;
    const int rowadd = (sel & 1) * 8;
    const int kselb  = (sel >> 1) * 16;

    float acc[2][8][4];
    #pragma unroll
    for (int i = 0; i < 2; i++)
        #pragma unroll
        for (int j = 0; j < 8; j++)
            #pragma unroll
            for (int c = 0; c < 4; c++) acc[i][j][c] = 0.f;

    auto load_chunk = [&](int chunk, int s) {
        const int k0 = chunk * KC;
        const uint32_t st = base + s * STAGE_B;
        #pragma unroll
        for (int t = 0; t < 4; t++) {
            int idx = tid + t * 256;
            int row = idx >> 3;
            int c16 = idx & 7;
            uint32_t off = SW128((uint32_t)(row * 128 + c16 * 16));
            const size_t g = (size_t)row * EMB + k0 + c16 * 8;
            cpasync16(st + 0*TILE_B + off, Ahi + g);
            cpasync16(st + 1*TILE_B + off, Alo + g);
            cpasync16(st + 2*TILE_B + off, Bhi + g);
            cpasync16(st + 3*TILE_B + off, Blo + g);
        }
    };

    load_chunk(0, 0); CP_COMMIT();
    load_chunk(1, 1); CP_COMMIT();
    load_chunk(2, 2); CP_COMMIT();

    for (int i = 0; i < NCHUNK; i++) {
        const int s = i - (i / 3) * 3;
        CP_WAIT2();
        __syncthreads();

        const uint32_t st   = base + s * STAGE_B;
        const uint32_t aHiB = st;
        const uint32_t aLoB = st + TILE_B;
        const uint32_t bHiB = st + 2*TILE_B;
        const uint32_t bLoB = st + 3*TILE_B;

        #pragma unroll
        for (int kk = 0; kk < 4; kk++) {
            const int kb = kk * 32;

            uint32_t ahi[2][4], alo[2][4];
            #pragma unroll
            for (int f = 0; f < 2; f++) {
                int row = wm*32 + f*16 + rowadd + lr;
                uint32_t byte = (uint32_t)(kb + kselb) ^ (uint32_t)((row & 7) * 16);
                uint32_t off  = (uint32_t)row * 128 + byte;
                ldsm4(ahi[f], aHiB + off);
                ldsm4(alo[f], aLoB + off);
            }
            uint32_t bhi[8][2], blo[8][2];
            #pragma unroll
            for (int jj = 0; jj < 4; jj++) {
                int row = wn*64 + jj*16 + rowadd + lr;
                uint32_t byte = (uint32_t)(kb + kselb) ^ (uint32_t)((row & 7) * 16);
                uint32_t off  = (uint32_t)row * 128 + byte;
                uint32_t t[4];
                ldsm4(t, bHiB + off);
                bhi[2*jj][0]   = t[0]; bhi[2*jj][1]   = t[2];
                bhi[2*jj+1][0] = t[1]; bhi[2*jj+1][1] = t[3];
                ldsm4(t, bLoB + off);
                blo[2*jj][0]   = t[0]; blo[2*jj][1]   = t[2];
                blo[2*jj+1][0] = t[1]; blo[2*jj+1][1] = t[3];
            }
            #pragma unroll
            for (int f = 0; f < 2; f++)
                #pragma unroll
                for (int j = 0; j < 8; j++) {
                    mma16816(acc[f][j], ahi[f], bhi[j][0], bhi[j][1]);
                    mma16816(acc[f][j], ahi[f], blo[j][0], blo[j][1]);
                    mma16816(acc[f][j], alo[f], bhi[j][0], bhi[j][1]);
                }
        }

        __syncthreads();
        if (i + 3 < NCHUNK) load_chunk(i + 3, s);
        CP_COMMIT();
    }

    // Epilogue: bias (+RoPE for Q,K), write bf16 hi/lo splits.
    const bool rope = (mat < 2);
    #pragma unroll
    for (int f = 0; f < 2; f++) {
        #pragma unroll
        for (int j = 0; j < 8; j++) {
            int c = wn*64 + j*8 + (lane & 3)*2;
            float b0v = bias[c], b1v = bias[c + 1];
            #pragma unroll
            for (int h = 0; h < 2; h++) {
                int row  = m0 + wm*32 + f*16 + (lane >> 2) + h*8;
                int spos = row & (SEQ - 1);
                float a = acc[f][j][2*h]     + b0v;
                float b = acc[f][j][2*h + 1] + b1v;
                if (rope) {
                    float cs = g_cos[spos*64 + (c >> 1)];
                    float sn = g_sin[spos*64 + (c >> 1)];
                    float ra = a*cs - b*sn;
                    float rb = b*cs + a*sn;
                    a = ra; b = rb;
                }
                uint32_t hi, lo;
                split_pack(a, b, hi, lo);
                if (mat == 0) {
                    *(uint32_t*)&g_Qhi[(size_t)row*HD + c] = hi;
                    *(uint32_t*)&g_Qlo[(size_t)row*HD + c] = lo;
                } else if (mat == 1) {
                    *(uint32_t*)&g_Khi[(size_t)row*HD + c] = hi;
                    *(uint32_t*)&g_Klo[(size_t)row*HD + c] = lo;
                } else {
                    // V transposed: [b][d][s]
                    size_t vb = ((size_t)(row >> 12) * HD) * SEQ + (row & (SEQ-1));
                    __nv_bfloat162 H = *(__nv_bfloat162*)&hi;
                    __nv_bfloat162 L = *(__nv_bfloat162*)&lo;
                    g_Vthi[vb + (size_t)c*SEQ]     = H.x;
                    g_Vthi[vb + (size_t)(c+1)*SEQ] = H.y;
                    g_Vtlo[vb + (size_t)c*SEQ]     = L.x;
                    g_Vtlo[vb + (size_t)(c+1)*SEQ] = L.y;
                }
            }
        }
    }
}

// ---------------------------------------------------------------------------
// Flash attention on mma.sync: BM=64, BN=64, 4 warps, bf16 3-term split for
// S=QK^T and PV. Register-resident softmax (quad shuffles), P never hits smem.
// smem: Q(hi/lo) 32KB + K(hi/lo) 32KB + Vt(hi/lo) 32KB = 96KB, 2 CTAs/SM.
// ---------------------------------------------------------------------------
#define ATTN_SMEM (96*1024 + 1024)

__global__ __launch_bounds__(128, 2) void attn_mma_kernel(float* __restrict__ out)
{
    extern __shared__ char sm_raw[];
    const uint32_t base = (smem_u32(sm_raw) + 1023) & ~1023u;
    const uint32_t QHI = base,          QLO = base + 16384;
    const uint32_t KHI = base + 32768,  KLO = base + 49152;
    const uint32_t VTHI = base + 65536, VTLO = base + 81920;

    const int tid  = threadIdx.x;
    const int wid  = tid >> 5;
    const int lane = tid & 31;
    const int lr     = lane & 7;
    const int sel    = lane >> 3;
    const int rowadd = (sel & 1) * 8;
    const int kselb  = (sel >> 1) * 16;

    // Balanced causal task map (work(qt)=qt+1; smid ~ bx%148):
    //   bx 108..147 -> biggest 40 tasks (single-CTA SMs)
    //   bx 0..107 pair with bx+148 -> work sums ~constant
    int bxx = blockIdx.x, t;
    if (bxx < 108)      t = 40 + bxx;
    else if (bxx < 148) t = bxx - 108;
    else                t = 403 - bxx;
    const int qt = 63 - (t >> 2);
    const int b  = t & 3;
    const int m0 = qt * 64;

    const __nv_bfloat16* qhi = g_Qhi + ((size_t)b*SEQ + m0) * HD;
    const __nv_bfloat16* qlo = g_Qlo + ((size_t)b*SEQ + m0) * HD;
    const __nv_bfloat16* khi = g_Khi + (size_t)b*SEQ*HD;
    const __nv_bfloat16* klo = g_Klo + (size_t)b*SEQ*HD;
    const __nv_bfloat16* vthi = g_Vthi + (size_t)b*HD*SEQ;
    const __nv_bfloat16* vtlo = g_Vtlo + (size_t)b*HD*SEQ;

    // Load Q tile once: 64 rows x 128 d bf16, two 64-d blocks of 128B rows.
    #pragma unroll
    for (int it = 0; it < 8; it++) {
        int i = tid + it * 128;
        int row = i >> 4, c = i & 15;
        uint32_t off = (uint32_t)((c >> 3) * 8192)
                     + SW128((uint32_t)(row * 128 + (c & 7) * 16));
        cpasync16(QHI + off, qhi + (size_t)row * HD + c * 8);
        cpasync16(QLO + off, qlo + (size_t)row * HD + c * 8);
    }
    CP_COMMIT();

    float o[16][4];
    #pragma unroll
    for (int nf = 0; nf < 16; nf++)
        #pragma unroll
        for (int c = 0; c < 4; c++) o[nf][c] = 0.f;
    float mrow0 = -INFINITY, mrow1 = -INFINITY;
    float lsum0 = 0.f, lsum1 = 0.f;
    const float scale = 0.08838834764831845f;   // 1/sqrt(128)

    for (int nt = 0; nt <= qt; nt++) {
        const int nb = nt * 64;
        if (nt) __syncthreads();   // all warps done reading previous K/V

        // K tile: 64 rows x 128 d (two blocks)
        #pragma unroll
        for (int it = 0; it < 8; it++) {
            int i = tid + it * 128;
            int row = i >> 4, c = i & 15;
            uint32_t off = (uint32_t)((c >> 3) * 8192)
                         + SW128((uint32_t)(row * 128 + (c & 7) * 16));
            const size_t g = (size_t)(nb + row) * HD + c * 8;
            cpasync16(KHI + off, khi + g);
            cpasync16(KLO + off, klo + g);
        }
        // Vt tile: 128 d-rows x 64 keys (single block, 128B rows)
        #pragma unroll
        for (int it = 0; it < 8; it++) {
            int i = tid + it * 128;
            int d = i >> 3, c = i & 7;
            uint32_t off = SW128((uint32_t)(d * 128 + c * 16));
            const size_t g = (size_t)d * SEQ + nb + c * 8;
            cpasync16(VTHI + off, vthi + g);
            cpasync16(VTLO + off, vtlo + g);
        }
        CP_COMMIT();
        CP_WAIT0();
        __syncthreads();

        // ---- S = Q K^T (3-term split) ----
        float s[8][4];
        #pragma unroll
        for (int j = 0; j < 8; j++)
            #pragma unroll
            for (int c = 0; c < 4; c++) s[j][c] = 0.f;

        #pragma unroll
        for (int kd = 0; kd < 8; kd++) {
            const uint32_t blk = (uint32_t)((kd >> 2) * 8192);
            const uint32_t kb  = (uint32_t)((kd & 3) * 32 + kselb);
            uint32_t ahi[4], alo[4];
            {
                int row = wid*16 + rowadd + lr;
                uint32_t addr = blk + (uint32_t)row*128 + (kb ^ (uint32_t)((row & 7)*16));
                ldsm4(ahi, QHI + addr);
                ldsm4(alo, QLO + addr);
            }
            #pragma unroll
            for (int jj = 0; jj < 4; jj++) {
                int row = jj*16 + rowadd + lr;
                uint32_t addr = blk + (uint32_t)row*128 + (kb ^ (uint32_t)((row & 7)*16));
                uint32_t th[4], tl[4];
                ldsm4(th, KHI + addr);
                ldsm4(tl, KLO + addr);
                mma16816(s[2*jj],   ahi, th[0], th[2]);
                mma16816(s[2*jj],   ahi, tl[0], tl[2]);
                mma16816(s[2*jj],   alo, th[0], th[2]);
                mma16816(s[2*jj+1], ahi, th[1], th[3]);
                mma16816(s[2*jj+1], ahi, tl[1], tl[3]);
                mma16816(s[2*jj+1], alo, th[1], th[3]);
            }
        }

        // ---- scale + causal mask ----
        const bool diag = (nt == qt);
        #pragma unroll
        for (int j = 0; j < 8; j++)
            #pragma unroll
            for (int c = 0; c < 4; c++) {
                float v = s[j][c] * scale;
                if (diag) {
                    int col = j*8 + (lane & 3)*2 + (c & 1);
                    int row = wid*16 + (lane >> 2) + (c >> 1)*8;
                    if (col > row) v = -1e30f;
                }
                s[j][c] = v;
            }

        // ---- online softmax (register + quad shuffle) ----
        float mx0 = -INFINITY, mx1 = -INFINITY;
        #pragma unroll
        for (int j = 0; j < 8; j++) {
            mx0 = fmaxf(mx0, fmaxf(s[j][0], s[j][1]));
            mx1 = fmaxf(mx1, fmaxf(s[j][2], s[j][3]));
        }
        mx0 = fmaxf(mx0, __shfl_xor_sync(0xffffffffu, mx0, 1));
        mx0 = fmaxf(mx0, __shfl_xor_sync(0xffffffffu, mx0, 2));
        mx1 = fmaxf(mx1, __shfl_xor_sync(0xffffffffu, mx1, 1));
        mx1 = fmaxf(mx1, __shfl_xor_sync(0xffffffffu, mx1, 2));
        float mn0 = fmaxf(mrow0, mx0), mn1 = fmaxf(mrow1, mx1);
        float al0 = __expf(mrow0 - mn0), al1 = __expf(mrow1 - mn1);
        mrow0 = mn0; mrow1 = mn1;
        float sum0 = 0.f, sum1 = 0.f;
        #pragma unroll
        for (int j = 0; j < 8; j++) {
            s[j][0] = __expf(s[j][0] - mn0); sum0 += s[j][0];
            s[j][1] = __expf(s[j][1] - mn0); sum0 += s[j][1];
            s[j][2] = __expf(s[j][2] - mn1); sum1 += s[j][2];
            s[j][3] = __expf(s[j][3] - mn1); sum1 += s[j][3];
        }
        sum0 += __shfl_xor_sync(0xffffffffu, sum0, 1);
        sum0 += __shfl_xor_sync(0xffffffffu, sum0, 2);
        sum1 += __shfl_xor_sync(0xffffffffu, sum1, 1);
        sum1 += __shfl_xor_sync(0xffffffffu, sum1, 2);
        lsum0 = lsum0 * al0 + sum0;
        lsum1 = lsum1 * al1 + sum1;

        // rescale O
        #pragma unroll
        for (int nf = 0; nf < 16; nf++) {
            o[nf][0] *= al0; o[nf][1] *= al0;
            o[nf][2] *= al1; o[nf][3] *= al1;
        }

        // ---- P -> bf16 hi/lo A-frags (C-frag -> A-frag identity) ----
        uint32_t phi[4][4], plo[4][4];
        #pragma unroll
        for (int kk = 0; kk < 4; kk++) {
            split_pack(s[2*kk][0],   s[2*kk][1],   phi[kk][0], plo[kk][0]);
            split_pack(s[2*kk][2],   s[2*kk][3],   phi[kk][1], plo[kk][1]);
            split_pack(s[2*kk+1][0], s[2*kk+1][1], phi[kk][2], plo[kk][2]);
            split_pack(s[2*kk+1][2], s[2*kk+1][3], phi[kk][3], plo[kk][3]);
        }

        // ---- O += P @ V (3-term split) ----
        #pragma unroll
        for (int kk = 0; kk < 4; kk++) {
            const uint32_t kb = (uint32_t)(kk*32 + kselb);
            #pragma unroll
            for (int jj = 0; jj < 8; jj++) {
                int row = jj*16 + rowadd + lr;   // d-row
                uint32_t addr = (uint32_t)row*128 + (kb ^ (uint32_t)((row & 7)*16));
                uint32_t th[4], tl[4];
                ldsm4(th, VTHI + addr);
                ldsm4(tl, VTLO + addr);
                mma16816(o[2*jj],   phi[kk], th[0], th[2]);
                mma16816(o[2*jj],   phi[kk], tl[0], tl[2]);
                mma16816(o[2*jj],   plo[kk], th[0], th[2]);
                mma16816(o[2*jj+1], phi[kk], th[1], th[3]);
                mma16816(o[2*jj+1], phi[kk], tl[1], tl[3]);
                mma16816(o[2*jj+1], plo[kk], th[1], th[3]);
            }
        }
    }

    // ---- normalize + write ----
    const float inv0 = 1.0f / lsum0;
    const float inv1 = 1.0f / lsum1;
    const size_t r0 = ((size_t)b*SEQ + m0 + wid*16 + (lane >> 2)) * HD;
    #pragma unroll
    for (int nf = 0; nf < 16; nf++) {
        int c = nf*8 + (lane & 3)*2;
        *(float2*)&out[r0 + c]          = make_float2(o[nf][0]*inv0, o[nf][1]*inv0);
        *(float2*)&out[r0 + 8*HD + c]   = make_float2(o[nf][2]*inv1, o[nf][3]*inv1);
    }
}

// ---------------------------------------------------------------------------
extern "C" void kernel_launch(void* const* d_in, const int* in_sizes, int n_in,
                              void* d_out, int out_size)
{
    const float* x  = (const float*)d_in[0];
    const float* Wq = (const float*)d_in[1];
    const float* bq = (const float*)d_in[2];
    const float* Wk = (const float*)d_in[3];
    const float* bk = (const float*)d_in[4];
    const float* Wv = (const float*)d_in[5];
    const float* bv = (const float*)d_in[6];
    float* out = (float*)d_out;

    rope_table_kernel<<<(SEQ*(HD/2) + 255)/256, 256>>>();
    split_x_kernel<<<(MTOT*(EMB/4) + 255)/256, 256>>>(x);
    split_w_kernel<<<(3*EMB*HD + 255)/256, 256>>>(Wq, Wk, Wv);

    cudaFuncSetAttribute(qkv_mma_kernel,
                         cudaFuncAttributeMaxDynamicSharedMemorySize, QKV_SMEM);
    dim3 g1(3, MTOT / 128);
    qkv_mma_kernel<<<g1, 256, QKV_SMEM>>>(bq, bk, bv);

    cudaFuncSetAttribute(attn_mma_kernel,
                         cudaFuncAttributeMaxDynamicSharedMemorySize, ATTN_SMEM);
    attn_mma_kernel<<<256, 128, ATTN_SMEM>>>(out);
}